// round 1
// baseline (speedup 1.0000x reference)
#include <cuda_runtime.h>
#include <cstdint>

// Problem constants
constexpr int S_LEN = 4096;
constexpr int DM    = 1024;
constexpr int NH    = 16;
constexpr int HD    = 64;      // head dim
constexpr int QKV_N = 3 * DM;  // 3072

// Scratch (device globals: allocation-free per harness rules)
__device__ float g_qkv[(size_t)S_LEN * QKV_N];   // [S, 3*D]  (q|k|v each [S, H*Hd])
__device__ float g_att[(size_t)S_LEN * DM];      // attention output [S, D]

// ---------------------------------------------------------------------------
// SGEMM: C[M,N] = A[M,K] * B[N,K]^T    (both operands K-major row-major)
// BM=BN=128, BK=16, 256 threads, 8x8 register tile per thread.
// Requires M%128==0, N%128==0, K%16==0 (true for all our shapes).
// ---------------------------------------------------------------------------
__global__ __launch_bounds__(256) void gemm_abT(
    const float* __restrict__ A, const float* __restrict__ B,
    float* __restrict__ C, int M, int N, int K)
{
    constexpr int BM = 128, BN = 128, BK = 16;
    __shared__ float As[BK][BM];
    __shared__ float Bs[BK][BN];

    const int tid = threadIdx.x;
    const int tx  = tid & 15;     // 0..15 -> N direction
    const int ty  = tid >> 4;     // 0..15 -> M direction
    const int m0  = blockIdx.y * BM;
    const int n0  = blockIdx.x * BN;

    float acc[8][8];
#pragma unroll
    for (int i = 0; i < 8; ++i)
#pragma unroll
        for (int j = 0; j < 8; ++j) acc[i][j] = 0.f;

    for (int k0 = 0; k0 < K; k0 += BK) {
        // Load 128x16 tiles of A and B, store transposed into shared.
#pragma unroll
        for (int p = 0; p < 2; ++p) {
            int idx = tid + p * 256;          // 0..511 (128 rows x 4 float4)
            int row = idx >> 2;
            int c4  = (idx & 3) * 4;
            float4 va = *(const float4*)&A[(size_t)(m0 + row) * K + k0 + c4];
            As[c4 + 0][row] = va.x; As[c4 + 1][row] = va.y;
            As[c4 + 2][row] = va.z; As[c4 + 3][row] = va.w;
            float4 vb = *(const float4*)&B[(size_t)(n0 + row) * K + k0 + c4];
            Bs[c4 + 0][row] = vb.x; Bs[c4 + 1][row] = vb.y;
            Bs[c4 + 2][row] = vb.z; Bs[c4 + 3][row] = vb.w;
        }
        __syncthreads();

#pragma unroll
        for (int kk = 0; kk < BK; ++kk) {
            float a[8], b[8];
            *(float4*)&a[0] = *(const float4*)&As[kk][ty * 8];
            *(float4*)&a[4] = *(const float4*)&As[kk][ty * 8 + 4];
            *(float4*)&b[0] = *(const float4*)&Bs[kk][tx * 8];
            *(float4*)&b[4] = *(const float4*)&Bs[kk][tx * 8 + 4];
#pragma unroll
            for (int i = 0; i < 8; ++i)
#pragma unroll
                for (int j = 0; j < 8; ++j)
                    acc[i][j] += a[i] * b[j];
        }
        __syncthreads();
    }

#pragma unroll
    for (int i = 0; i < 8; ++i) {
        float* crow = &C[(size_t)(m0 + ty * 8 + i) * N + n0 + tx * 8];
        *(float4*)&crow[0] = make_float4(acc[i][0], acc[i][1], acc[i][2], acc[i][3]);
        *(float4*)&crow[4] = make_float4(acc[i][4], acc[i][5], acc[i][6], acc[i][7]);
    }
}

// ---------------------------------------------------------------------------
// Flash attention (fp32, causal). One block = (head h, 64-row Q tile).
// 256 threads as a 16x16 grid; each thread owns a 4x4 sub-tile of the 64x64
// S tile and of the 64x64 O tile. Online softmax. P staged through shared.
// Dynamic shared layout:
//   Qt[64][68]  (d-major: Qt[d][r])
//   Kt[64][68]  (d-major: Kt[d][c])
//   Ps[64][68]  (t-major: Ps[t][r])
//   Vs[64][64]  (row-major: Vs[t][d])
// ---------------------------------------------------------------------------
constexpr int PAD = 68;                // 68*4B = 272B rows: 16B aligned, few conflicts
constexpr int FLASH_SMEM = (3 * 64 * PAD + 64 * 64) * (int)sizeof(float);  // 68608 B

__global__ __launch_bounds__(256) void flash_fp32(
    const float* __restrict__ qkv, float* __restrict__ out)
{
    extern __shared__ float sm[];
    float* Qt = sm;                    // [64][PAD]
    float* Kt = Qt + 64 * PAD;         // [64][PAD]
    float* Ps = Kt + 64 * PAD;         // [64][PAD]
    float* Vs = Ps + 64 * PAD;         // [64][64]

    const int tid = threadIdx.x;
    const int tx  = tid & 15;          // KV cols / d cols
    const int ty  = tid >> 4;          // Q rows
    const int h   = blockIdx.y;
    const int qt  = (int)gridDim.x - 1 - (int)blockIdx.x;  // heavy tiles first
    const int q0  = qt * 64;

    const int row_stride = QKV_N;      // 3072 floats per token row
    const float* qbase = qkv + (size_t)q0 * row_stride + h * HD;

    // Load Q tile transposed: Qt[d][r]
#pragma unroll
    for (int p = 0; p < 4; ++p) {
        int idx = tid + p * 256;       // 0..1023 : 64 rows x 16 float4
        int row = idx >> 4;
        int c4  = (idx & 15) * 4;
        float4 v = *(const float4*)&qbase[(size_t)row * row_stride + c4];
        Qt[(c4 + 0) * PAD + row] = v.x; Qt[(c4 + 1) * PAD + row] = v.y;
        Qt[(c4 + 2) * PAD + row] = v.z; Qt[(c4 + 3) * PAD + row] = v.w;
    }
    __syncthreads();

    float m_i[4], l_i[4], accO[4][4];
#pragma unroll
    for (int i = 0; i < 4; ++i) {
        m_i[i] = -1e30f; l_i[i] = 0.f;
#pragma unroll
        for (int j = 0; j < 4; ++j) accO[i][j] = 0.f;
    }

    for (int t = 0; t <= qt; ++t) {
        const float* kbase = qkv + (size_t)(t * 64) * row_stride + DM + h * HD;
        const float* vbase = kbase + DM;

        // Load K transposed (Kt[d][c]) and V row-major (Vs[t][d])
#pragma unroll
        for (int p = 0; p < 4; ++p) {
            int idx = tid + p * 256;
            int row = idx >> 4;
            int c4  = (idx & 15) * 4;
            float4 kv4 = *(const float4*)&kbase[(size_t)row * row_stride + c4];
            Kt[(c4 + 0) * PAD + row] = kv4.x; Kt[(c4 + 1) * PAD + row] = kv4.y;
            Kt[(c4 + 2) * PAD + row] = kv4.z; Kt[(c4 + 3) * PAD + row] = kv4.w;
            float4 vv4 = *(const float4*)&vbase[(size_t)row * row_stride + c4];
            *(float4*)&Vs[row * 64 + c4] = vv4;
        }
        __syncthreads();

        // S = Q K^T (scaled)
        float s[4][4];
#pragma unroll
        for (int i = 0; i < 4; ++i)
#pragma unroll
            for (int j = 0; j < 4; ++j) s[i][j] = 0.f;

#pragma unroll 8
        for (int kk = 0; kk < 64; ++kk) {
            float4 q4 = *(const float4*)&Qt[kk * PAD + ty * 4];
            float4 k4 = *(const float4*)&Kt[kk * PAD + tx * 4];
            float qa[4] = {q4.x, q4.y, q4.z, q4.w};
            float kb[4] = {k4.x, k4.y, k4.z, k4.w};
#pragma unroll
            for (int i = 0; i < 4; ++i)
#pragma unroll
                for (int j = 0; j < 4; ++j)
                    s[i][j] += qa[i] * kb[j];
        }

        const float scale = 0.125f;    // 64^-0.5
#pragma unroll
        for (int i = 0; i < 4; ++i)
#pragma unroll
            for (int j = 0; j < 4; ++j) s[i][j] *= scale;

        if (t == qt) {                 // diagonal tile: causal mask
#pragma unroll
            for (int i = 0; i < 4; ++i) {
                int qr = ty * 4 + i;
#pragma unroll
                for (int j = 0; j < 4; ++j)
                    if (tx * 4 + j > qr) s[i][j] = -1e30f;
            }
        }

        // Online softmax per row (row group = 16 lanes sharing ty, width-16 shfl)
#pragma unroll
        for (int i = 0; i < 4; ++i) {
            float mx = fmaxf(fmaxf(s[i][0], s[i][1]), fmaxf(s[i][2], s[i][3]));
#pragma unroll
            for (int off = 8; off > 0; off >>= 1)
                mx = fmaxf(mx, __shfl_xor_sync(0xffffffffu, mx, off, 16));
            float mnew  = fmaxf(m_i[i], mx);
            float alpha = __expf(m_i[i] - mnew);
            m_i[i] = mnew;
            float rsum = 0.f;
#pragma unroll
            for (int j = 0; j < 4; ++j) {
                float pv = __expf(s[i][j] - mnew);
                s[i][j] = pv;
                rsum += pv;
            }
#pragma unroll
            for (int off = 8; off > 0; off >>= 1)
                rsum += __shfl_xor_sync(0xffffffffu, rsum, off, 16);
            l_i[i] = l_i[i] * alpha + rsum;
#pragma unroll
            for (int j = 0; j < 4; ++j) accO[i][j] *= alpha;
        }

        // Stage P transposed: Ps[t][r]
#pragma unroll
        for (int i = 0; i < 4; ++i)
#pragma unroll
            for (int j = 0; j < 4; ++j)
                Ps[(tx * 4 + j) * PAD + ty * 4 + i] = s[i][j];
        __syncthreads();

        // O += P V
#pragma unroll 8
        for (int kk = 0; kk < 64; ++kk) {
            float4 p4 = *(const float4*)&Ps[kk * PAD + ty * 4];
            float4 v4 = *(const float4*)&Vs[kk * 64 + tx * 4];
            float pa[4] = {p4.x, p4.y, p4.z, p4.w};
            float vb[4] = {v4.x, v4.y, v4.z, v4.w};
#pragma unroll
            for (int i = 0; i < 4; ++i)
#pragma unroll
                for (int j = 0; j < 4; ++j)
                    accO[i][j] += pa[i] * vb[j];
        }
        __syncthreads();               // before next tile overwrites Kt/Vs/Ps
    }

    // Write O/l to g_att: [s, h*Hd + d]
#pragma unroll
    for (int i = 0; i < 4; ++i) {
        float inv = 1.f / l_i[i];
        float4 o = make_float4(accO[i][0] * inv, accO[i][1] * inv,
                               accO[i][2] * inv, accO[i][3] * inv);
        *(float4*)&out[(size_t)(q0 + ty * 4 + i) * DM + h * HD + tx * 4] = o;
    }
}

// ---------------------------------------------------------------------------
// Launch
// ---------------------------------------------------------------------------
extern "C" void kernel_launch(void* const* d_in, const int* in_sizes, int n_in,
                              void* d_out, int out_size)
{
    const float* x     = (const float*)d_in[0];   // [1,4096,1024]
    const float* w_qkv = (const float*)d_in[1];   // [3072,1024]
    const float* w_out = (const float*)d_in[2];   // [1024,1024]
    float* out = (float*)d_out;                   // [1,4096,1024]

    float* qkv_ptr = nullptr;
    float* att_ptr = nullptr;
    cudaGetSymbolAddress((void**)&qkv_ptr, g_qkv);
    cudaGetSymbolAddress((void**)&att_ptr, g_att);

    cudaFuncSetAttribute(flash_fp32, cudaFuncAttributeMaxDynamicSharedMemorySize,
                         FLASH_SMEM);

    // 1) QKV projection: [4096,3072] = x [4096,1024] @ w_qkv^T
    {
        dim3 grid(QKV_N / 128, S_LEN / 128);
        gemm_abT<<<grid, 256>>>(x, w_qkv, qkv_ptr, S_LEN, QKV_N, DM);
    }
    // 2) Flash attention per (q-tile, head)
    {
        dim3 grid(S_LEN / 64, NH);
        flash_fp32<<<grid, 256, FLASH_SMEM>>>(qkv_ptr, att_ptr);
    }
    // 3) Output projection: [4096,1024] = att [4096,1024] @ w_out^T
    {
        dim3 grid(DM / 128, S_LEN / 128);
        gemm_abT<<<grid, 256>>>(att_ptr, w_out, out, S_LEN, DM, DM);
    }
}

// round 3
// speedup vs baseline: 3.6625x; 3.6625x over previous
#include <cuda_runtime.h>
#include <cstdint>

// Problem constants
constexpr int S_LEN = 4096;
constexpr int DM    = 1024;
constexpr int NH    = 16;
constexpr int HD    = 64;
constexpr int QKV_N = 3 * DM;  // 3072

// Scratch device globals (allocation-free rule)
__device__ float g_x   [(size_t)S_LEN * DM];     // tf32-rounded x
__device__ float g_wqkv[(size_t)QKV_N * DM];     // tf32-rounded w_qkv
__device__ float g_wout[(size_t)DM * DM];        // tf32-rounded w_out
__device__ float g_qkv [(size_t)S_LEN * QKV_N];  // qkv (tf32-rounded)
__device__ float g_att [(size_t)S_LEN * DM];     // attention out (tf32-rounded)

// ---------------------------------------------------------------------------
// Helpers
// ---------------------------------------------------------------------------
__device__ __forceinline__ float tf32r(float x) {
    uint32_t u;
    asm("cvt.rna.tf32.f32 %0, %1;" : "=r"(u) : "f"(x));
    return __uint_as_float(u);
}

__device__ __forceinline__ void cp_async16(void* smem_dst, const void* gmem_src) {
    uint32_t s = (uint32_t)__cvta_generic_to_shared(smem_dst);
    asm volatile("cp.async.cg.shared.global [%0], [%1], 16;" :: "r"(s), "l"(gmem_src));
}
__device__ __forceinline__ void cp_commit() {
    asm volatile("cp.async.commit_group;");
}
template<int N>
__device__ __forceinline__ void cp_wait() {
    asm volatile("cp.async.wait_group %0;" :: "n"(N));
}

// m16n8k8 tf32 mma: D += A*B. a[4], b[2] hold tf32 bit patterns in fp32 regs.
__device__ __forceinline__ void mma_tf32(float c[4], const float a[4],
                                         float b0, float b1) {
    asm volatile(
        "mma.sync.aligned.m16n8k8.row.col.f32.tf32.tf32.f32 "
        "{%0,%1,%2,%3}, {%4,%5,%6,%7}, {%8,%9}, {%0,%1,%2,%3};"
        : "+f"(c[0]), "+f"(c[1]), "+f"(c[2]), "+f"(c[3])
        : "r"(__float_as_uint(a[0])), "r"(__float_as_uint(a[1])),
          "r"(__float_as_uint(a[2])), "r"(__float_as_uint(a[3])),
          "r"(__float_as_uint(b0)),  "r"(__float_as_uint(b1)));
}

// ---------------------------------------------------------------------------
// Elementwise tf32 rounding pre-pass
// ---------------------------------------------------------------------------
__global__ void cvt_tf32_kernel(const float* __restrict__ in,
                                float* __restrict__ out, int n4) {
    int i = blockIdx.x * blockDim.x + threadIdx.x;
    if (i < n4) {
        float4 v = ((const float4*)in)[i];
        v.x = tf32r(v.x); v.y = tf32r(v.y);
        v.z = tf32r(v.z); v.w = tf32r(v.w);
        ((float4*)out)[i] = v;
    }
}

// ---------------------------------------------------------------------------
// TF32 tensor-core GEMM: C[M,N] = A[M,K] * B[N,K]^T  (A,B pre-rounded tf32)
// Block 128x128x32, 256 threads (8 warps of 64x32). cp.async double buffer.
// Smem: As[2][128][36] (m-major), Bs[2][128][36] (n-major).  73728 B dynamic.
// ---------------------------------------------------------------------------
constexpr int GEMM_SMEM = 2 * 2 * 128 * 36 * (int)sizeof(float);

template<bool ROUND_OUT>
__global__ __launch_bounds__(256) void gemm_tf32(
    const float* __restrict__ A, const float* __restrict__ B,
    float* __restrict__ C, int M, int N, int K)
{
    extern __shared__ float sm[];
    float* AsBase = sm;                 // 2 * 128*36
    float* BsBase = sm + 2 * 128 * 36;  // 2 * 128*36

    const int tid  = threadIdx.x;
    const int lane = tid & 31;
    const int wid  = tid >> 5;
    const int wm   = (wid >> 2) * 64;   // warp m offset in block tile
    const int wn   = (wid & 3) * 32;    // warp n offset
    const int m0   = blockIdx.y * 128;
    const int n0   = blockIdx.x * 128;

    const int ldr = tid >> 3;           // 0..31 row group per pass
    const int ldc = (tid & 7) * 4;      // 0..28 col (float4)

    const int NI = K / 32;

    auto issue_tile = [&](int it, int buf) {
        const float* Ag = A + (size_t)(m0) * K + it * 32;
        const float* Bg = B + (size_t)(n0) * K + it * 32;
        float* As = AsBase + buf * (128 * 36);
        float* Bs = BsBase + buf * (128 * 36);
#pragma unroll
        for (int p = 0; p < 4; ++p) {
            int row = p * 32 + ldr;
            cp_async16(&As[row * 36 + ldc], &Ag[(size_t)row * K + ldc]);
            cp_async16(&Bs[row * 36 + ldc], &Bg[(size_t)row * K + ldc]);
        }
        cp_commit();
    };

    float acc[4][4][4];
#pragma unroll
    for (int i = 0; i < 4; ++i)
#pragma unroll
        for (int j = 0; j < 4; ++j)
#pragma unroll
            for (int c = 0; c < 4; ++c) acc[i][j][c] = 0.f;

    issue_tile(0, 0);

    for (int it = 0; it < NI; ++it) {
        if (it + 1 < NI) {
            issue_tile(it + 1, (it + 1) & 1);
            cp_wait<1>();
        } else {
            cp_wait<0>();
        }
        __syncthreads();

        const float* As = AsBase + (it & 1) * (128 * 36);
        const float* Bs = BsBase + (it & 1) * (128 * 36);

#pragma unroll
        for (int kk = 0; kk < 4; ++kk) {
            const int kb = kk * 8 + (lane & 3);
            float a[4][4];
#pragma unroll
            for (int mt = 0; mt < 4; ++mt) {
                int r = wm + mt * 16 + (lane >> 2);
                a[mt][0] = As[r * 36 + kb];
                a[mt][1] = As[(r + 8) * 36 + kb];
                a[mt][2] = As[r * 36 + kb + 4];
                a[mt][3] = As[(r + 8) * 36 + kb + 4];
            }
#pragma unroll
            for (int nt = 0; nt < 4; ++nt) {
                int cI = wn + nt * 8 + (lane >> 2);
                float b0 = Bs[cI * 36 + kb];
                float b1 = Bs[cI * 36 + kb + 4];
#pragma unroll
                for (int mt = 0; mt < 4; ++mt)
                    mma_tf32(acc[mt][nt], a[mt], b0, b1);
            }
        }
        __syncthreads();
    }

    // Epilogue
#pragma unroll
    for (int mt = 0; mt < 4; ++mt) {
#pragma unroll
        for (int nt = 0; nt < 4; ++nt) {
            int row = m0 + wm + mt * 16 + (lane >> 2);
            int col = n0 + wn + nt * 8 + 2 * (lane & 3);
            float v0 = acc[mt][nt][0], v1 = acc[mt][nt][1];
            float v2 = acc[mt][nt][2], v3 = acc[mt][nt][3];
            if (ROUND_OUT) { v0 = tf32r(v0); v1 = tf32r(v1); v2 = tf32r(v2); v3 = tf32r(v3); }
            *(float2*)&C[(size_t)row * N + col]       = make_float2(v0, v1);
            *(float2*)&C[(size_t)(row + 8) * N + col] = make_float2(v2, v3);
        }
    }
}

// ---------------------------------------------------------------------------
// Flash attention (tf32 mma, causal). Block = (64-row Q tile, head).
// 128 threads / 4 warps; warp w owns q rows [w*16, w*16+16).
// Smem: Qs[64][68], Ps[64][68], Ks[2][64][68], Vs[2][64][72] = 106496 B.
// ---------------------------------------------------------------------------
constexpr int FL_SMEM = (2 * 64 * 68 + 2 * 64 * 68 + 2 * 64 * 72) * (int)sizeof(float);

__global__ __launch_bounds__(128) void flash_tf32(
    const float* __restrict__ qkv, float* __restrict__ out)
{
    extern __shared__ float sm[];
    float* Qs = sm;                        // 64*68
    float* Ps = Qs + 64 * 68;              // 64*68
    float* KsB = Ps + 64 * 68;             // 2 * 64*68
    float* VsB = KsB + 2 * 64 * 68;        // 2 * 64*72

    const int tid  = threadIdx.x;
    const int lane = tid & 31;
    const int w    = tid >> 5;
    const int h    = blockIdx.y;
    const int qt   = (int)gridDim.x - 1 - (int)blockIdx.x;  // heavy first
    const int q0   = qt * 64;

    const int ldr = tid >> 4;              // 0..7
    const int ldc = (tid & 15) * 4;        // 0..60

    const float* qg = qkv + (size_t)q0 * QKV_N + h * HD;

    auto issue_kv = [&](int t, int buf) {
        const float* kg = qkv + (size_t)(t * 64) * QKV_N + DM + h * HD;
        const float* vg = kg + DM;
        float* Ks = KsB + buf * (64 * 68);
        float* Vs = VsB + buf * (64 * 72);
#pragma unroll
        for (int p = 0; p < 8; ++p) {
            int row = p * 8 + ldr;
            cp_async16(&Ks[row * 68 + ldc], &kg[(size_t)row * QKV_N + ldc]);
            cp_async16(&Vs[row * 72 + ldc], &vg[(size_t)row * QKV_N + ldc]);
        }
        cp_commit();
    };

    // Prologue: Q + KV tile 0 in one group
    {
#pragma unroll
        for (int p = 0; p < 8; ++p) {
            int row = p * 8 + ldr;
            cp_async16(&Qs[row * 68 + ldc], &qg[(size_t)row * QKV_N + ldc]);
        }
    }
    issue_kv(0, 0);

    const int r  = (lane >> 2);            // 0..7
    const int qr = w * 16 + r;             // this thread's first q row (local)
    float m_i[2] = {-1e30f, -1e30f};
    float l_i[2] = {0.f, 0.f};
    float oacc[8][4];
#pragma unroll
    for (int n = 0; n < 8; ++n)
#pragma unroll
        for (int c = 0; c < 4; ++c) oacc[n][c] = 0.f;

    for (int t = 0; t <= qt; ++t) {
        if (t < qt) { issue_kv(t + 1, (t + 1) & 1); cp_wait<1>(); }
        else        { cp_wait<0>(); }
        __syncthreads();

        const float* Ks = KsB + (t & 1) * (64 * 68);
        const float* Vs = VsB + (t & 1) * (64 * 72);

        // S = Q K^T
        float sacc[8][4];
#pragma unroll
        for (int n = 0; n < 8; ++n)
#pragma unroll
            for (int c = 0; c < 4; ++c) sacc[n][c] = 0.f;

#pragma unroll
        for (int kt = 0; kt < 8; ++kt) {
            const int kb = kt * 8 + (lane & 3);
            float a[4];
            a[0] = Qs[qr * 68 + kb];
            a[1] = Qs[(qr + 8) * 68 + kb];
            a[2] = Qs[qr * 68 + kb + 4];
            a[3] = Qs[(qr + 8) * 68 + kb + 4];
#pragma unroll
            for (int nt = 0; nt < 8; ++nt) {
                int cI = nt * 8 + (lane >> 2);
                float b0 = Ks[cI * 68 + kb];
                float b1 = Ks[cI * 68 + kb + 4];
                mma_tf32(sacc[nt], a, b0, b1);
            }
        }

        // scale + causal mask (diagonal tile only)
        const float scale = 0.125f;
#pragma unroll
        for (int nt = 0; nt < 8; ++nt)
#pragma unroll
            for (int c = 0; c < 4; ++c) sacc[nt][c] *= scale;

        if (t == qt) {
#pragma unroll
            for (int nt = 0; nt < 8; ++nt) {
#pragma unroll
                for (int c = 0; c < 4; ++c) {
                    int col = nt * 8 + 2 * (lane & 3) + (c & 1);
                    int rowL = qr + (c >> 1) * 8;
                    if (col > rowL) sacc[nt][c] = -1e30f;
                }
            }
        }

        // Online softmax: rows qr (c=0,1) and qr+8 (c=2,3)
        float alpha[2];
#pragma unroll
        for (int half = 0; half < 2; ++half) {
            float mx = -1e30f;
#pragma unroll
            for (int nt = 0; nt < 8; ++nt) {
                mx = fmaxf(mx, sacc[nt][half * 2]);
                mx = fmaxf(mx, sacc[nt][half * 2 + 1]);
            }
            mx = fmaxf(mx, __shfl_xor_sync(0xffffffffu, mx, 1, 4));
            mx = fmaxf(mx, __shfl_xor_sync(0xffffffffu, mx, 2, 4));
            float mnew = fmaxf(m_i[half], mx);
            alpha[half] = __expf(m_i[half] - mnew);
            m_i[half] = mnew;
            float rs = 0.f;
#pragma unroll
            for (int nt = 0; nt < 8; ++nt) {
                float p0 = __expf(sacc[nt][half * 2]     - mnew);
                float p1 = __expf(sacc[nt][half * 2 + 1] - mnew);
                sacc[nt][half * 2]     = p0;
                sacc[nt][half * 2 + 1] = p1;
                rs += p0 + p1;
            }
            rs += __shfl_xor_sync(0xffffffffu, rs, 1, 4);
            rs += __shfl_xor_sync(0xffffffffu, rs, 2, 4);
            l_i[half] = l_i[half] * alpha[half] + rs;
        }

        // Rescale O accumulators
#pragma unroll
        for (int nt = 0; nt < 8; ++nt) {
            oacc[nt][0] *= alpha[0]; oacc[nt][1] *= alpha[0];
            oacc[nt][2] *= alpha[1]; oacc[nt][3] *= alpha[1];
        }

        // Stage P (tf32-rounded) into warp-private Ps rows
#pragma unroll
        for (int nt = 0; nt < 8; ++nt) {
            int col = nt * 8 + 2 * (lane & 3);
            Ps[qr * 68 + col]           = tf32r(sacc[nt][0]);
            Ps[qr * 68 + col + 1]       = tf32r(sacc[nt][1]);
            Ps[(qr + 8) * 68 + col]     = tf32r(sacc[nt][2]);
            Ps[(qr + 8) * 68 + col + 1] = tf32r(sacc[nt][3]);
        }
        __syncwarp();

        // O += P V
#pragma unroll
        for (int kt = 0; kt < 8; ++kt) {
            const int kb = kt * 8 + (lane & 3);
            float a[4];
            a[0] = Ps[qr * 68 + kb];
            a[1] = Ps[(qr + 8) * 68 + kb];
            a[2] = Ps[qr * 68 + kb + 4];
            a[3] = Ps[(qr + 8) * 68 + kb + 4];
#pragma unroll
            for (int nt = 0; nt < 8; ++nt) {
                int dI = nt * 8 + (lane >> 2);
                float b0 = Vs[kb * 72 + dI];
                float b1 = Vs[(kb + 4) * 72 + dI];
                mma_tf32(oacc[nt], a, b0, b1);
            }
        }
        __syncthreads();   // protect K/V buffer reuse and Ps vs next S write
    }

    // Epilogue: normalize, round to tf32, store
    float inv0 = 1.f / l_i[0];
    float inv1 = 1.f / l_i[1];
#pragma unroll
    for (int nt = 0; nt < 8; ++nt) {
        int col = h * HD + nt * 8 + 2 * (lane & 3);
        int row = q0 + qr;
        *(float2*)&out[(size_t)row * DM + col] =
            make_float2(tf32r(oacc[nt][0] * inv0), tf32r(oacc[nt][1] * inv0));
        *(float2*)&out[(size_t)(row + 8) * DM + col] =
            make_float2(tf32r(oacc[nt][2] * inv1), tf32r(oacc[nt][3] * inv1));
    }
}

// ---------------------------------------------------------------------------
// Launch
// ---------------------------------------------------------------------------
extern "C" void kernel_launch(void* const* d_in, const int* in_sizes, int n_in,
                              void* d_out, int out_size)
{
    const float* x     = (const float*)d_in[0];
    const float* w_qkv = (const float*)d_in[1];
    const float* w_out = (const float*)d_in[2];
    float* out = (float*)d_out;

    float *xr, *wqkvr, *woutr, *qkvp, *attp;
    cudaGetSymbolAddress((void**)&xr,    g_x);
    cudaGetSymbolAddress((void**)&wqkvr, g_wqkv);
    cudaGetSymbolAddress((void**)&woutr, g_wout);
    cudaGetSymbolAddress((void**)&qkvp,  g_qkv);
    cudaGetSymbolAddress((void**)&attp,  g_att);

    cudaFuncSetAttribute(gemm_tf32<true>,
                         cudaFuncAttributeMaxDynamicSharedMemorySize, GEMM_SMEM);
    cudaFuncSetAttribute(gemm_tf32<false>,
                         cudaFuncAttributeMaxDynamicSharedMemorySize, GEMM_SMEM);
    cudaFuncSetAttribute(flash_tf32,
                         cudaFuncAttributeMaxDynamicSharedMemorySize, FL_SMEM);

    // 0) tf32-round the inputs
    {
        int n4;
        n4 = S_LEN * DM / 4;
        cvt_tf32_kernel<<<(n4 + 255) / 256, 256>>>(x, xr, n4);
        n4 = QKV_N * DM / 4;
        cvt_tf32_kernel<<<(n4 + 255) / 256, 256>>>(w_qkv, wqkvr, n4);
        n4 = DM * DM / 4;
        cvt_tf32_kernel<<<(n4 + 255) / 256, 256>>>(w_out, woutr, n4);
    }
    // 1) QKV projection (round output for attention mma consumption)
    {
        dim3 grid(QKV_N / 128, S_LEN / 128);
        gemm_tf32<true><<<grid, 256, GEMM_SMEM>>>(xr, wqkvr, qkvp, S_LEN, QKV_N, DM);
    }
    // 2) Flash attention (rounds its own output)
    {
        dim3 grid(S_LEN / 64, NH);
        flash_tf32<<<grid, 128, FL_SMEM>>>(qkvp, attp);
    }
    // 3) Output projection (full fp32 out)
    {
        dim3 grid(DM / 128, S_LEN / 128);
        gemm_tf32<false><<<grid, 256, GEMM_SMEM>>>(attp, woutr, out, S_LEN, DM, DM);
    }
}